// round 5
// baseline (speedup 1.0000x reference)
#include <cuda_runtime.h>
#include <cuda_bf16.h>
#include <cstdint>

#define BB   64
#define NN   2048
#define SS   512
#define NCTA 64
#define TPB  256
#define CPC  32          // columns per CTA
#define KBLK 64
#define NKB  (NN/KBLK)   // 32
#define KPAD 72          // bf16 elems per smem row (144B: 16B aligned, conflict-free)

__device__ __nv_bfloat16 g_Wt[(size_t)NN * NN];  // W_rec transposed: [n][k]
__device__ __nv_bfloat16 g_e[2][BB * NN];        // unnormalized exp(z), double-buffered
__device__ float g_Sp[2][NCTA][BB];              // per-CTA row-sum partials
__device__ unsigned g_flags[NCTA];               // grid barrier flags

// ---- transpose + convert W_rec (fp32 [k][n]) -> g_Wt (bf16 [n][k]) ----
__global__ void k_prep(const float* __restrict__ W) {
    __shared__ float tile[32][33];
    int bx = blockIdx.x, by = blockIdx.y, tx = threadIdx.x, ty = threadIdx.y;
#pragma unroll
    for (int i = 0; i < 4; i++) {
        int k = by * 32 + ty + i * 8;
        tile[ty + i * 8][tx] = W[(size_t)k * NN + bx * 32 + tx];
    }
    __syncthreads();
#pragma unroll
    for (int i = 0; i < 4; i++) {
        int n = bx * 32 + ty + i * 8;
        g_Wt[(size_t)n * NN + by * 32 + tx] = __float2bfloat16(tile[tx][ty + i * 8]);
    }
}

// ---- seed e_{-1}=h0 (bf16), s_{-1}=1 (partials), reset barrier flags ----
__global__ void k_init(const float* __restrict__ h0) {
    int i = blockIdx.x * blockDim.x + threadIdx.x;
    if (i < BB * NN) g_e[1][i] = __float2bfloat16(h0[i]);
    if (i < NCTA * BB) (&g_Sp[1][0][0])[i] = (i < BB) ? 1.f : 0.f;
    if (i < NCTA) g_flags[i] = 0u;
}

__device__ __forceinline__ void cp16(unsigned d, const void* s) {
    asm volatile("cp.async.cg.shared.global [%0],[%1],16;" :: "r"(d), "l"(s) : "memory");
}
__device__ __forceinline__ void cpcommit() {
    asm volatile("cp.async.commit_group;" ::: "memory");
}

__device__ __forceinline__ void grid_bar(int tid, unsigned tgt) {
    __syncthreads();
    if (tid == 0)
        asm volatile("st.release.gpu.u32 [%0], %1;" :: "l"(&g_flags[blockIdx.x]), "r"(tgt) : "memory");
    if (tid < NCTA) {
        unsigned v;
        do {
            asm volatile("ld.acquire.gpu.u32 %0, [%1];" : "=r"(v) : "l"(&g_flags[tid]) : "memory");
        } while (v < tgt);
    }
    __syncthreads();
}

__global__ void __launch_bounds__(TPB, 1) k_step(
    const float* __restrict__ vel, const float* __restrict__ Wlin,
    const float* __restrict__ blin, float* __restrict__ out)
{
    __shared__ __align__(16) __nv_bfloat16 sA[3][BB][KPAD];
    __shared__ __align__(16) __nv_bfloat16 sW[3][CPC][KPAD];
    __shared__ float sV0[BB], sV1[BB], sInv[BB], sWp[2][BB];

    const int tid = threadIdx.x;
    const int w = tid >> 5, l = tid & 31;
    const int g = l >> 2, tg = l & 3;
    const int mrow0 = (w & 3) * 16;       // batch-row base for this warp
    const int nloc0 = (w >> 2) * 16;      // local column base for this warp
    const int ccol0 = blockIdx.x * CPC;
    const int r0 = mrow0 + g, r1 = r0 + 8;

    // per-thread columns + linear-layer constants
    float wl0[4], wl1[4], bl4[4]; int ncg[4];
#pragma unroll
    for (int j = 0; j < 2; j++)
#pragma unroll
        for (int q = 0; q < 2; q++) {
            int idx = j * 2 + q;
            int n = ccol0 + nloc0 + j * 8 + tg * 2 + q;
            ncg[idx] = n; wl0[idx] = Wlin[n * 2]; wl1[idx] = Wlin[n * 2 + 1]; bl4[idx] = blin[n];
        }

    // ldmatrix per-lane base addresses (stage 0)
    unsigned aAddr = (unsigned)__cvta_generic_to_shared(&sA[0][mrow0 + (l & 15)][(l & 16) ? 8 : 0]);
    int bq = l >> 3;
    unsigned bAddr = (unsigned)__cvta_generic_to_shared(&sW[0][nloc0 + ((bq & 2) ? 8 : 0) + (l & 7)][(bq & 1) ? 8 : 0]);
    const unsigned ASTG = BB * KPAD * 2u, WSTG = CPC * KPAD * 2u;

    auto load_stage = [&](int st, int k0, const __nv_bfloat16* eprev) {
#pragma unroll
        for (int ch = tid; ch < 512; ch += TPB) {          // A: 64 rows x 8 chunks
            int r = ch >> 3, cc = ch & 7;
            cp16((unsigned)__cvta_generic_to_shared(&sA[st][r][cc * 8]),
                 eprev + (size_t)r * NN + k0 + cc * 8);
        }
        {                                                  // W: 32 rows x 8 chunks
            int r = tid >> 3, cc = tid & 7;
            cp16((unsigned)__cvta_generic_to_shared(&sW[st][r][cc * 8]),
                 g_Wt + (size_t)(ccol0 + r) * NN + k0 + cc * 8);
        }
        cpcommit();
    };

    float acc[2][4];
#pragma unroll
    for (int j = 0; j < 2; j++)
#pragma unroll
        for (int q = 0; q < 4; q++) acc[j][q] = 0.f;
    float ek[8];

    for (int t = 0; t < SS; t++) {
        const int pb = (t + 1) & 1;
        const __nv_bfloat16* eprev = g_e[pb];

        // prefetch stages 0,1
        load_stage(0, 0, eprev);
        load_stage(1, KBLK, eprev);

        // s_{t-1} = sum of 64 CTA partials (deterministic), + stage velocities
        if (tid < BB) {
            float s = 0.f;
#pragma unroll 8
            for (int c = 0; c < NCTA; c++) s += __ldcg(&g_Sp[pb][c][tid]);
            sInv[tid] = 1.f / s;
            float2 v = *(const float2*)&vel[((size_t)tid * SS + t) * 2];
            sV0[tid] = v.x; sV1[tid] = v.y;
        }
        __syncthreads();
        const float is0 = sInv[r0], is1 = sInv[r1];

        // deferred normalized output for step t-1
        if (t > 0) {
#pragma unroll
            for (int j = 0; j < 2; j++) {
                *(float2*)&out[((size_t)r0 * SS + (t - 1)) * NN + ncg[j * 2]] =
                    make_float2(ek[j * 2] * is0, ek[j * 2 + 1] * is0);
                *(float2*)&out[((size_t)r1 * SS + (t - 1)) * NN + ncg[j * 2]] =
                    make_float2(ek[4 + j * 2] * is1, ek[4 + j * 2 + 1] * is1);
            }
        }

        // ---- GEMM: acc = e_prev @ Wt[cols], 3-stage cp.async pipeline ----
#pragma unroll 1
        for (int kb = 0; kb < NKB; kb++) {
            const int cur = kb % 3;
            if (kb < NKB - 2) asm volatile("cp.async.wait_group 1;" ::: "memory");
            else              asm volatile("cp.async.wait_group 0;" ::: "memory");
            __syncthreads();
            if (kb + 2 < NKB) load_stage((kb + 2) % 3, (kb + 2) * KBLK, eprev);
            const unsigned aB = aAddr + cur * ASTG, bB = bAddr + cur * WSTG;
#pragma unroll
            for (int kk = 0; kk < KBLK; kk += 16) {
                unsigned a0, a1, a2, a3, b0, b1, b2, b3;
                asm volatile("ldmatrix.sync.aligned.m8n8.x4.shared.b16 {%0,%1,%2,%3},[%4];"
                             : "=r"(a0), "=r"(a1), "=r"(a2), "=r"(a3) : "r"(aB + kk * 2u));
                asm volatile("ldmatrix.sync.aligned.m8n8.x4.shared.b16 {%0,%1,%2,%3},[%4];"
                             : "=r"(b0), "=r"(b1), "=r"(b2), "=r"(b3) : "r"(bB + kk * 2u));
                asm volatile("mma.sync.aligned.m16n8k16.row.col.f32.bf16.bf16.f32 "
                             "{%0,%1,%2,%3},{%4,%5,%6,%7},{%8,%9},{%0,%1,%2,%3};"
                             : "+f"(acc[0][0]), "+f"(acc[0][1]), "+f"(acc[0][2]), "+f"(acc[0][3])
                             : "r"(a0), "r"(a1), "r"(a2), "r"(a3), "r"(b0), "r"(b1));
                asm volatile("mma.sync.aligned.m16n8k16.row.col.f32.bf16.bf16.f32 "
                             "{%0,%1,%2,%3},{%4,%5,%6,%7},{%8,%9},{%0,%1,%2,%3};"
                             : "+f"(acc[1][0]), "+f"(acc[1][1]), "+f"(acc[1][2]), "+f"(acc[1][3])
                             : "r"(a0), "r"(a1), "r"(a2), "r"(a3), "r"(b2), "r"(b3));
            }
        }

        // ---- epilogue: z = lin + zrec/s_prev ; e = exp(z) ----
        float se0 = 0.f, se1 = 0.f;
#pragma unroll
        for (int j = 0; j < 2; j++)
#pragma unroll
            for (int q = 0; q < 2; q++) {
                int idx = j * 2 + q;
                float lin0 = fmaf(sV0[r0], wl0[idx], fmaf(sV1[r0], wl1[idx], bl4[idx]));
                float lin1 = fmaf(sV0[r1], wl0[idx], fmaf(sV1[r1], wl1[idx], bl4[idx]));
                float e0 = __expf(fmaf(acc[j][q],     is0, lin0));
                float e1 = __expf(fmaf(acc[j][2 + q], is1, lin1));
                ek[idx] = e0; ek[4 + idx] = e1;
                se0 += e0; se1 += e1;
                acc[j][q] = 0.f; acc[j][2 + q] = 0.f;
            }
        __nv_bfloat16* ecur = g_e[t & 1];
#pragma unroll
        for (int j = 0; j < 2; j++) {
            *(__nv_bfloat162*)&ecur[(size_t)r0 * NN + ncg[j * 2]] =
                __floats2bfloat162_rn(ek[j * 2], ek[j * 2 + 1]);
            *(__nv_bfloat162*)&ecur[(size_t)r1 * NN + ncg[j * 2]] =
                __floats2bfloat162_rn(ek[4 + j * 2], ek[4 + j * 2 + 1]);
        }
        // deterministic row partial sums: 4-lane shuffle then per-warp slot
        se0 += __shfl_xor_sync(0xffffffffu, se0, 1); se0 += __shfl_xor_sync(0xffffffffu, se0, 2);
        se1 += __shfl_xor_sync(0xffffffffu, se1, 1); se1 += __shfl_xor_sync(0xffffffffu, se1, 2);
        if (tg == 0) { sWp[w >> 2][r0] = se0; sWp[w >> 2][r1] = se1; }
        __syncthreads();
        if (tid < BB) __stcg(&g_Sp[t & 1][blockIdx.x][tid], sWp[0][tid] + sWp[1][tid]);

        grid_bar(tid, (unsigned)(t + 1));
    }

    // ---- final step output (t = SS-1) ----
    if (tid < BB) {
        float s = 0.f;
#pragma unroll 8
        for (int c = 0; c < NCTA; c++) s += __ldcg(&g_Sp[(SS - 1) & 1][c][tid]);
        sInv[tid] = 1.f / s;
    }
    __syncthreads();
    {
        const float is0 = sInv[r0], is1 = sInv[r1];
#pragma unroll
        for (int j = 0; j < 2; j++) {
            *(float2*)&out[((size_t)r0 * SS + (SS - 1)) * NN + ncg[j * 2]] =
                make_float2(ek[j * 2] * is0, ek[j * 2 + 1] * is0);
            *(float2*)&out[((size_t)r1 * SS + (SS - 1)) * NN + ncg[j * 2]] =
                make_float2(ek[4 + j * 2] * is1, ek[4 + j * 2 + 1] * is1);
        }
    }
}

extern "C" void kernel_launch(void* const* d_in, const int* in_sizes, int n_in,
                              void* d_out, int out_size) {
    const float* vel  = (const float*)d_in[0];
    const float* h0   = (const float*)d_in[1];
    const float* Wlin = (const float*)d_in[2];
    const float* blin = (const float*)d_in[3];
    const float* Wrec = (const float*)d_in[4];
    float* out = (float*)d_out;
    k_prep<<<dim3(NN / 32, NN / 32), dim3(32, 8)>>>(Wrec);
    k_init<<<(BB * NN + 255) / 256, 256>>>(h0);
    k_step<<<NCTA, TPB>>>(vel, Wlin, blin, out);
}

// round 6
// speedup vs baseline: 1.4807x; 1.4807x over previous
#include <cuda_runtime.h>
#include <cuda_bf16.h>
#include <cstdint>

#define BB   64
#define NN   2048
#define SS   512
#define NCTA 64
#define TPB  256
#define CPC  32          // columns per CTA
#define KBLK 256
#define NKB  (NN/KBLK)   // 8
#define PIPE 3
#define ROWB 512                 // bytes per tile row (256 k-elems bf16)
#define A_STG (BB*ROWB)          // 32768
#define W_STG (CPC*ROWB)         // 16384
#define STG_TX (A_STG + W_STG)   // 49152

// Global scratch (pre-swizzled tiled layouts; chunk16 index XOR (row&7))
__device__ __align__(128) unsigned char g_W2[(size_t)NCTA * NKB * W_STG]; // 8MB
__device__ __align__(128) unsigned char g_e2[2][NKB * A_STG];             // 2x256KB
__device__ float g_Sp[2][NCTA][BB];
__device__ unsigned g_flags[NCTA];

// ---- prep: W_rec fp32 [k][n] -> g_W2 bf16 tiled [cta][kb][row=n_local][swizzled 512B] ----
__global__ void k_prep(const float* __restrict__ W) {
    __shared__ float s[256][33];
    const int tid = threadIdx.x;
    const int cta = blockIdx.x;       // n-tile (32 cols)
    const int kb  = blockIdx.y;       // k-tile (256)
    const int n0 = cta * 32, k0 = kb * 256;
    for (int idx = tid; idx < 256 * 32; idx += TPB) {
        int k = idx >> 5, nl = idx & 31;
        s[k][nl] = W[(size_t)(k0 + k) * NN + n0 + nl];
    }
    __syncthreads();
    unsigned char* dst = g_W2 + ((size_t)cta * NKB + kb) * W_STG;
    for (int it = tid; it < 32 * 32; it += TPB) {
        int rl = it >> 5, ch = it & 31;   // row-local, 16B-chunk (8 k-elems)
        __nv_bfloat16 v[8];
#pragma unroll
        for (int j = 0; j < 8; j++) v[j] = __float2bfloat16(s[ch * 8 + j][rl]);
        *(uint4*)(dst + rl * ROWB + ((ch ^ (rl & 7)) << 4)) = *(uint4*)v;
    }
}

// ---- init: h0 -> g_e2[1] (tiled+swizzled bf16), seed partials, reset flags ----
__global__ void k_init(const float* __restrict__ h0) {
    int item = blockIdx.x * TPB + threadIdx.x;     // 64 blocks x 256 = 16384
    if (item < BB * NN / 8) {
        int b = item >> 8, ch = item & 255;        // chunk of 8 n
        __nv_bfloat16 v[8];
        const float* src = h0 + (size_t)b * NN + ch * 8;
#pragma unroll
        for (int j = 0; j < 8; j++) v[j] = __float2bfloat16(src[j]);
        int kb = ch >> 5, chl = ch & 31;
        unsigned char* dst = g_e2[1] + (size_t)kb * A_STG + b * ROWB + ((chl ^ (b & 7)) << 4);
        *(uint4*)dst = *(uint4*)v;
    }
    if (item < NCTA * BB) (&g_Sp[1][0][0])[item] = (item < BB) ? 1.f : 0.f;
    if (item < NCTA) g_flags[item] = 0u;
}

__device__ __forceinline__ void mbar_init(unsigned mb, unsigned cnt) {
    asm volatile("mbarrier.init.shared.b64 [%0], %1;" :: "r"(mb), "r"(cnt) : "memory");
}
__device__ __forceinline__ void mbar_expect(unsigned mb, unsigned bytes) {
    asm volatile("mbarrier.arrive.expect_tx.shared.b64 _, [%0], %1;" :: "r"(mb), "r"(bytes) : "memory");
}
__device__ __forceinline__ void bulk_ld(unsigned dst, const void* src, unsigned bytes, unsigned mb) {
    asm volatile("cp.async.bulk.shared::cluster.global.mbarrier::complete_tx::bytes [%0], [%1], %2, [%3];"
                 :: "r"(dst), "l"(src), "r"(bytes), "r"(mb) : "memory");
}
__device__ __forceinline__ void mbar_wait(unsigned mb, unsigned ph) {
    asm volatile("{\n\t.reg .pred P;\n"
                 "W0_%=:\n\t"
                 "mbarrier.try_wait.parity.acquire.cta.shared::cta.b64 P, [%0], %1, 0x989680;\n\t"
                 "@P bra W1_%=;\n\t"
                 "bra W0_%=;\n"
                 "W1_%=:\n\t}"
                 :: "r"(mb), "r"(ph) : "memory");
}

__device__ __forceinline__ void grid_bar(int tid, unsigned tgt) {
    __syncthreads();
    if (tid == 0)
        asm volatile("st.release.gpu.u32 [%0], %1;" :: "l"(&g_flags[blockIdx.x]), "r"(tgt) : "memory");
    if (tid < NCTA) {
        unsigned v;
        do {
            asm volatile("ld.acquire.gpu.u32 %0, [%1];" : "=r"(v) : "l"(&g_flags[tid]) : "memory");
        } while (v < tgt);
    }
    __syncthreads();
}

#define ADV(s, p) do { if (++(s) == PIPE) { (s) = 0; (p) ^= 1; } } while (0)

extern __shared__ __align__(128) unsigned char dsm[];  // [3xA_STG][3xW_STG] = 144KB

__global__ void __launch_bounds__(TPB, 1) k_step(
    const float* __restrict__ vel, const float* __restrict__ Wlin,
    const float* __restrict__ blin, float* __restrict__ out)
{
    __shared__ float sV0[BB], sV1[BB], sInv[BB], sWp[2][BB];
    __shared__ __align__(8) unsigned long long mbar[PIPE];

    const int tid = threadIdx.x;
    const int w = tid >> 5, l = tid & 31;
    const int g = l >> 2, tg = l & 3;
    const int mrow0 = (w & 3) * 16;
    const int nloc0 = (w >> 2) * 16;
    const int ccol0 = blockIdx.x * CPC;
    const int r0 = mrow0 + g, r1 = r0 + 8;

    const unsigned smemA = (unsigned)__cvta_generic_to_shared(dsm);
    const unsigned smemW = smemA + PIPE * A_STG;
    unsigned mb[PIPE];
    if (tid == 0) {
#pragma unroll
        for (int p = 0; p < PIPE; p++)
            mbar_init((unsigned)__cvta_generic_to_shared(&mbar[p]), 1u);
    }
#pragma unroll
    for (int p = 0; p < PIPE; p++) mb[p] = (unsigned)__cvta_generic_to_shared(&mbar[p]);
    __syncthreads();

    // per-thread output columns + linear-layer constants
    float wl0[4], wl1[4], bl4[4]; int ncg[4];
#pragma unroll
    for (int j = 0; j < 2; j++)
#pragma unroll
        for (int q = 0; q < 2; q++) {
            int idx = j * 2 + q;
            int n = ccol0 + nloc0 + j * 8 + tg * 2 + q;
            ncg[idx] = n; wl0[idx] = Wlin[n * 2]; wl1[idx] = Wlin[n * 2 + 1]; bl4[idx] = blin[n];
        }

    // ldmatrix per-lane row bases + swizzle params
    const int rowA = mrow0 + (l & 15);
    const int mA = rowA & 7, halfA = (l >> 4) & 1;
    const unsigned aRow = smemA + rowA * ROWB;
    const int bq = l >> 3;
    const int rowB = nloc0 + ((bq & 2) ? 8 : 0) + (l & 7);
    const int mB = rowB & 7, halfB = bq & 1;
    const unsigned bRow = smemW + rowB * ROWB;

    float acc[2][4];
#pragma unroll
    for (int j = 0; j < 2; j++)
#pragma unroll
        for (int q = 0; q < 4; q++) acc[j][q] = 0.f;
    float ek[8];

    int cs = 0, cph = 0;   // pipeline cursor (slot, phase)

    for (int t = 0; t < SS; t++) {
        const int pb = (t + 1) & 1;
        const unsigned char* eBuf = g_e2[pb];

        // prologue: issue PIPE stages immediately (overlap with sum/vel below)
        if (tid == 0) {
            int s2 = cs;
#pragma unroll
            for (int i = 0; i < PIPE; i++) {
                mbar_expect(mb[s2], STG_TX);
                bulk_ld(smemA + s2 * A_STG, eBuf + (size_t)i * A_STG, A_STG, mb[s2]);
                bulk_ld(smemW + s2 * W_STG,
                        g_W2 + ((size_t)blockIdx.x * NKB + i) * W_STG, W_STG, mb[s2]);
                s2 = (s2 + 1 == PIPE) ? 0 : s2 + 1;
            }
        }

        // s_{t-1} = sum of 64 CTA partials (8 independent chains for MLP) + velocities
        if (tid < BB) {
            const float* pp = &g_Sp[pb][0][0] + tid;
            float a0=0,a1=0,a2=0,a3=0,a4=0,a5=0,a6=0,a7=0;
#pragma unroll
            for (int c = 0; c < NCTA; c += 8) {
                a0 += __ldcg(pp + (c+0)*BB); a1 += __ldcg(pp + (c+1)*BB);
                a2 += __ldcg(pp + (c+2)*BB); a3 += __ldcg(pp + (c+3)*BB);
                a4 += __ldcg(pp + (c+4)*BB); a5 += __ldcg(pp + (c+5)*BB);
                a6 += __ldcg(pp + (c+6)*BB); a7 += __ldcg(pp + (c+7)*BB);
            }
            sInv[tid] = 1.f / (((a0+a1)+(a2+a3)) + ((a4+a5)+(a6+a7)));
            float2 v = *(const float2*)&vel[((size_t)tid * SS + t) * 2];
            sV0[tid] = v.x; sV1[tid] = v.y;
        }
        __syncthreads();
        const float is0 = sInv[r0], is1 = sInv[r1];

        // deferred normalized output for step t-1
        if (t > 0) {
#pragma unroll
            for (int j = 0; j < 2; j++) {
                *(float2*)&out[((size_t)r0 * SS + (t - 1)) * NN + ncg[j * 2]] =
                    make_float2(ek[j * 2] * is0, ek[j * 2 + 1] * is0);
                *(float2*)&out[((size_t)r1 * SS + (t - 1)) * NN + ncg[j * 2]] =
                    make_float2(ek[4 + j * 2] * is1, ek[4 + j * 2 + 1] * is1);
            }
        }

        // ---- GEMM: 8 K-stages of 256, TMA-bulk 3-stage pipeline ----
#pragma unroll 1
        for (int kb = 0; kb < NKB; kb++) {
            const int slot = cs;
            mbar_wait(mb[slot], (unsigned)cph);
            const unsigned aB = aRow + slot * A_STG;
            const unsigned bB = bRow + slot * W_STG;
#pragma unroll
            for (int kkIdx = 0; kkIdx < KBLK / 16; kkIdx++) {
                unsigned a0, a1, a2, a3, b0, b1, b2, b3;
                unsigned aA = aB + ((unsigned)((kkIdx * 2 + halfA) ^ mA) << 4);
                unsigned bA = bB + ((unsigned)((kkIdx * 2 + halfB) ^ mB) << 4);
                asm volatile("ldmatrix.sync.aligned.m8n8.x4.shared.b16 {%0,%1,%2,%3},[%4];"
                             : "=r"(a0), "=r"(a1), "=r"(a2), "=r"(a3) : "r"(aA));
                asm volatile("ldmatrix.sync.aligned.m8n8.x4.shared.b16 {%0,%1,%2,%3},[%4];"
                             : "=r"(b0), "=r"(b1), "=r"(b2), "=r"(b3) : "r"(bA));
                asm volatile("mma.sync.aligned.m16n8k16.row.col.f32.bf16.bf16.f32 "
                             "{%0,%1,%2,%3},{%4,%5,%6,%7},{%8,%9},{%0,%1,%2,%3};"
                             : "+f"(acc[0][0]), "+f"(acc[0][1]), "+f"(acc[0][2]), "+f"(acc[0][3])
                             : "r"(a0), "r"(a1), "r"(a2), "r"(a3), "r"(b0), "r"(b1));
                asm volatile("mma.sync.aligned.m16n8k16.row.col.f32.bf16.bf16.f32 "
                             "{%0,%1,%2,%3},{%4,%5,%6,%7},{%8,%9},{%0,%1,%2,%3};"
                             : "+f"(acc[1][0]), "+f"(acc[1][1]), "+f"(acc[1][2]), "+f"(acc[1][3])
                             : "r"(a0), "r"(a1), "r"(a2), "r"(a3), "r"(b2), "r"(b3));
            }
            __syncthreads();   // all warps done with this slot
            if (kb + PIPE < NKB && tid == 0) {
                mbar_expect(mb[slot], STG_TX);
                bulk_ld(smemA + slot * A_STG, eBuf + (size_t)(kb + PIPE) * A_STG, A_STG, mb[slot]);
                bulk_ld(smemW + slot * W_STG,
                        g_W2 + ((size_t)blockIdx.x * NKB + kb + PIPE) * W_STG, W_STG, mb[slot]);
            }
            ADV(cs, cph);
        }

        // ---- epilogue: z = lin + zrec/s_prev ; e = exp(z) ----
        float se0 = 0.f, se1 = 0.f;
#pragma unroll
        for (int j = 0; j < 2; j++)
#pragma unroll
            for (int q = 0; q < 2; q++) {
                int idx = j * 2 + q;
                float lin0 = fmaf(sV0[r0], wl0[idx], fmaf(sV1[r0], wl1[idx], bl4[idx]));
                float lin1 = fmaf(sV0[r1], wl0[idx], fmaf(sV1[r1], wl1[idx], bl4[idx]));
                float e0 = __expf(fmaf(acc[j][q],     is0, lin0));
                float e1 = __expf(fmaf(acc[j][2 + q], is1, lin1));
                ek[idx] = e0; ek[4 + idx] = e1;
                se0 += e0; se1 += e1;
                acc[j][q] = 0.f; acc[j][2 + q] = 0.f;
            }
        // store e into tiled+swizzled layout for next step's bulk loads
        unsigned char* ecur = g_e2[t & 1];
#pragma unroll
        for (int j = 0; j < 2; j++) {
            int n = ncg[j * 2];
            int kb2 = n >> 8, cb = (n & 255) * 2;
            unsigned sw0 = (unsigned)(((cb >> 4) ^ (r0 & 7)) << 4) | (cb & 15);
            unsigned sw1 = (unsigned)(((cb >> 4) ^ (r1 & 7)) << 4) | (cb & 15);
            *(__nv_bfloat162*)(ecur + (size_t)kb2 * A_STG + r0 * ROWB + sw0) =
                __floats2bfloat162_rn(ek[j * 2], ek[j * 2 + 1]);
            *(__nv_bfloat162*)(ecur + (size_t)kb2 * A_STG + r1 * ROWB + sw1) =
                __floats2bfloat162_rn(ek[4 + j * 2], ek[4 + j * 2 + 1]);
        }
        // deterministic per-CTA row partials
        se0 += __shfl_xor_sync(0xffffffffu, se0, 1); se0 += __shfl_xor_sync(0xffffffffu, se0, 2);
        se1 += __shfl_xor_sync(0xffffffffu, se1, 1); se1 += __shfl_xor_sync(0xffffffffu, se1, 2);
        if (tg == 0) { sWp[w >> 2][r0] = se0; sWp[w >> 2][r1] = se1; }
        __syncthreads();
        if (tid < BB) __stcg(&g_Sp[t & 1][blockIdx.x][tid], sWp[0][tid] + sWp[1][tid]);

        grid_bar(tid, (unsigned)(t + 1));
    }

    // ---- final step output (t = SS-1) ----
    if (tid < BB) {
        const float* pp = &g_Sp[(SS - 1) & 1][0][0] + tid;
        float s = 0.f;
#pragma unroll
        for (int c = 0; c < NCTA; c++) s += __ldcg(pp + c * BB);
        sInv[tid] = 1.f / s;
    }
    __syncthreads();
    {
        const float is0 = sInv[r0], is1 = sInv[r1];
#pragma unroll
        for (int j = 0; j < 2; j++) {
            *(float2*)&out[((size_t)r0 * SS + (SS - 1)) * NN + ncg[j * 2]] =
                make_float2(ek[j * 2] * is0, ek[j * 2 + 1] * is0);
            *(float2*)&out[((size_t)r1 * SS + (SS - 1)) * NN + ncg[j * 2]] =
                make_float2(ek[4 + j * 2] * is1, ek[4 + j * 2 + 1] * is1);
        }
    }
}

extern "C" void kernel_launch(void* const* d_in, const int* in_sizes, int n_in,
                              void* d_out, int out_size) {
    const float* vel  = (const float*)d_in[0];
    const float* h0   = (const float*)d_in[1];
    const float* Wlin = (const float*)d_in[2];
    const float* blin = (const float*)d_in[3];
    const float* Wrec = (const float*)d_in[4];
    float* out = (float*)d_out;
    static int configured = 0;
    if (!configured) {
        cudaFuncSetAttribute(k_step, cudaFuncAttributeMaxDynamicSharedMemorySize,
                             PIPE * (A_STG + W_STG));
        configured = 1;
    }
    k_prep<<<dim3(NCTA, NKB), TPB>>>(Wrec);
    k_init<<<BB, TPB>>>(h0);
    k_step<<<NCTA, TPB, PIPE * (A_STG + W_STG)>>>(vel, Wlin, blin, out);
}

// round 7
// speedup vs baseline: 1.6392x; 1.1071x over previous
#include <cuda_runtime.h>
#include <cuda_bf16.h>
#include <cstdint>

#define BB   64
#define NN   2048
#define SS   512
#define NCTA 64
#define TPB  256
#define CPC  32          // columns per CTA
#define KBLK 256
#define NKB  (NN/KBLK)   // 8
#define PIPE 3
#define ROWB 512                 // bytes per tile row (256 k-elems bf16)
#define A_STG (BB*ROWB)          // 32768
#define W_STG (CPC*ROWB)         // 16384
#define W_TOT (NKB*W_STG)        // 131072 (persistent in smem)
#define DSM_BYTES (W_TOT + PIPE*A_STG)   // 229376

// Global scratch (pre-swizzled tiled layouts; chunk16 index XOR (row&7))
__device__ __align__(128) unsigned char g_W2[(size_t)NCTA * W_TOT];   // 8MB
__device__ __align__(128) unsigned char g_e2[2][NKB * A_STG];         // 2x256KB
__device__ float g_Sp[2][NCTA][BB];
__device__ unsigned g_flags[NCTA];

// ---- setup: W_rec -> g_W2 (bf16 tiled+swizzled); h0 -> g_e2[1]; seed partials/flags ----
__global__ void k_setup(const float* __restrict__ W, const float* __restrict__ h0) {
    const int tid = threadIdx.x;
    if (blockIdx.y < NKB) {
        // prep: W fp32 [k][n] -> g_W2 [cta][kb][row=n_local][swizzled 512B]
        __shared__ float s[256][33];
        const int cta = blockIdx.x, kb = blockIdx.y;
        const int n0 = cta * 32, k0 = kb * 256;
        for (int idx = tid; idx < 256 * 32; idx += TPB) {
            int k = idx >> 5, nl = idx & 31;
            s[k][nl] = W[(size_t)(k0 + k) * NN + n0 + nl];
        }
        __syncthreads();
        unsigned char* dst = g_W2 + (size_t)cta * W_TOT + (size_t)kb * W_STG;
        for (int it = tid; it < 32 * 32; it += TPB) {
            int rl = it >> 5, ch = it & 31;
            __nv_bfloat16 v[8];
#pragma unroll
            for (int j = 0; j < 8; j++) v[j] = __float2bfloat16(s[ch * 8 + j][rl]);
            *(uint4*)(dst + rl * ROWB + ((ch ^ (rl & 7)) << 4)) = *(uint4*)v;
        }
    } else {
        // init: h0 -> g_e2[1] tiled+swizzled; partials; flags
        int item = blockIdx.x * TPB + tid;         // 64*256 = 16384 = BB*NN/8
        {
            int b = item >> 8, ch = item & 255;
            __nv_bfloat16 v[8];
            const float* src = h0 + (size_t)b * NN + ch * 8;
#pragma unroll
            for (int j = 0; j < 8; j++) v[j] = __float2bfloat16(src[j]);
            int kb = ch >> 5, chl = ch & 31;
            unsigned char* dst = g_e2[1] + (size_t)kb * A_STG + b * ROWB + ((chl ^ (b & 7)) << 4);
            *(uint4*)dst = *(uint4*)v;
        }
        if (item < NCTA * BB) (&g_Sp[1][0][0])[item] = (item < BB) ? 1.f : 0.f;
        if (item < NCTA) g_flags[item] = 0u;
    }
}

__device__ __forceinline__ void mbar_init(unsigned mb, unsigned cnt) {
    asm volatile("mbarrier.init.shared.b64 [%0], %1;" :: "r"(mb), "r"(cnt) : "memory");
}
__device__ __forceinline__ void mbar_expect(unsigned mb, unsigned bytes) {
    asm volatile("mbarrier.arrive.expect_tx.shared.b64 _, [%0], %1;" :: "r"(mb), "r"(bytes) : "memory");
}
__device__ __forceinline__ void bulk_ld(unsigned dst, const void* src, unsigned bytes, unsigned mb) {
    asm volatile("cp.async.bulk.shared::cluster.global.mbarrier::complete_tx::bytes [%0], [%1], %2, [%3];"
                 :: "r"(dst), "l"(src), "r"(bytes), "r"(mb) : "memory");
}
__device__ __forceinline__ void mbar_wait(unsigned mb, unsigned ph) {
    asm volatile("{\n\t.reg .pred P;\n"
                 "W0_%=:\n\t"
                 "mbarrier.try_wait.parity.acquire.cta.shared::cta.b64 P, [%0], %1, 0x989680;\n\t"
                 "@P bra W1_%=;\n\t"
                 "bra W0_%=;\n"
                 "W1_%=:\n\t}"
                 :: "r"(mb), "r"(ph) : "memory");
}

__device__ __forceinline__ void grid_bar(int tid, unsigned tgt) {
    __syncthreads();
    if (tid == 0)
        asm volatile("st.release.gpu.u32 [%0], %1;" :: "l"(&g_flags[blockIdx.x]), "r"(tgt) : "memory");
    if (tid < NCTA) {
        unsigned v;
        do {
            asm volatile("ld.acquire.gpu.u32 %0, [%1];" : "=r"(v) : "l"(&g_flags[tid]) : "memory");
        } while (v < tgt);
    }
    __syncthreads();
}

#define ADV(s, p) do { if (++(s) == PIPE) { (s) = 0; (p) ^= 1; } } while (0)

extern __shared__ __align__(128) unsigned char dsm[];  // [W 128KB][A 3x32KB]

__global__ void __launch_bounds__(TPB, 1) k_step(
    const float* __restrict__ vel, const float* __restrict__ Wlin,
    const float* __restrict__ blin, float* __restrict__ out)
{
    __shared__ float sV0[BB], sV1[BB], sInv[BB], sWp[2][BB];
    __shared__ __align__(8) unsigned long long mbar[PIPE + 1];   // [0..2]=A stages, [3]=W

    const int tid = threadIdx.x;
    const int w = tid >> 5, l = tid & 31;
    const int g = l >> 2, tg = l & 3;
    const int mrow0 = (w & 3) * 16;
    const int nloc0 = (w >> 2) * 16;
    const int ccol0 = blockIdx.x * CPC;
    const int r0 = mrow0 + g, r1 = r0 + 8;

    const unsigned smemW = (unsigned)__cvta_generic_to_shared(dsm);
    const unsigned smemA = smemW + W_TOT;
    unsigned mb[PIPE + 1];
#pragma unroll
    for (int p = 0; p < PIPE + 1; p++) mb[p] = (unsigned)__cvta_generic_to_shared(&mbar[p]);
    if (tid == 0) {
#pragma unroll
        for (int p = 0; p < PIPE + 1; p++) mbar_init(mb[p], 1u);
    }
    __syncthreads();

    // load persistent W slice (128KB) once, single bulk copy
    if (tid == 0) {
        mbar_expect(mb[PIPE], W_TOT);
        bulk_ld(smemW, g_W2 + (size_t)blockIdx.x * W_TOT, W_TOT, mb[PIPE]);
    }

    // per-thread output columns + linear-layer constants
    float wl0[4], wl1[4], bl4[4]; int ncg[4];
#pragma unroll
    for (int j = 0; j < 2; j++)
#pragma unroll
        for (int q = 0; q < 2; q++) {
            int idx = j * 2 + q;
            int n = ccol0 + nloc0 + j * 8 + tg * 2 + q;
            ncg[idx] = n; wl0[idx] = Wlin[n * 2]; wl1[idx] = Wlin[n * 2 + 1]; bl4[idx] = blin[n];
        }

    // ldmatrix per-lane row bases + swizzle params
    const int rowA = mrow0 + (l & 15);
    const int mA = rowA & 7, halfA = (l >> 4) & 1;
    const unsigned aRow = smemA + rowA * ROWB;
    const int bq = l >> 3;
    const int rowB = nloc0 + ((bq & 2) ? 8 : 0) + (l & 7);
    const int mB = rowB & 7, halfB = bq & 1;
    const unsigned bRow = smemW + rowB * ROWB;

    float acc[2][4];
#pragma unroll
    for (int j = 0; j < 2; j++)
#pragma unroll
        for (int q = 0; q < 4; q++) acc[j][q] = 0.f;
    float ek[8];

    // wait for W once (off critical path)
    mbar_wait(mb[PIPE], 0u);
    __syncthreads();

    int cs = 0, cph = 0;   // A-pipeline cursor (slot, phase)

    for (int t = 0; t < SS; t++) {
        const int pb = (t + 1) & 1;
        const unsigned char* eBuf = g_e2[pb];

        // prologue: issue PIPE A-stages immediately (overlap with sum/vel below)
        if (tid == 0) {
            int s2 = cs;
#pragma unroll
            for (int i = 0; i < PIPE; i++) {
                mbar_expect(mb[s2], A_STG);
                bulk_ld(smemA + s2 * A_STG, eBuf + (size_t)i * A_STG, A_STG, mb[s2]);
                s2 = (s2 + 1 == PIPE) ? 0 : s2 + 1;
            }
        }

        // s_{t-1} = sum of 64 CTA partials (8 independent chains) + velocities
        if (tid < BB) {
            const float* pp = &g_Sp[pb][0][0] + tid;
            float a0=0,a1=0,a2=0,a3=0,a4=0,a5=0,a6=0,a7=0;
#pragma unroll
            for (int c = 0; c < NCTA; c += 8) {
                a0 += __ldcg(pp + (c+0)*BB); a1 += __ldcg(pp + (c+1)*BB);
                a2 += __ldcg(pp + (c+2)*BB); a3 += __ldcg(pp + (c+3)*BB);
                a4 += __ldcg(pp + (c+4)*BB); a5 += __ldcg(pp + (c+5)*BB);
                a6 += __ldcg(pp + (c+6)*BB); a7 += __ldcg(pp + (c+7)*BB);
            }
            sInv[tid] = 1.f / (((a0+a1)+(a2+a3)) + ((a4+a5)+(a6+a7)));
            float2 v = *(const float2*)&vel[((size_t)tid * SS + t) * 2];
            sV0[tid] = v.x; sV1[tid] = v.y;
        }
        __syncthreads();
        const float is0 = sInv[r0], is1 = sInv[r1];

        // deferred normalized output for step t-1
        if (t > 0) {
#pragma unroll
            for (int j = 0; j < 2; j++) {
                *(float2*)&out[((size_t)r0 * SS + (t - 1)) * NN + ncg[j * 2]] =
                    make_float2(ek[j * 2] * is0, ek[j * 2 + 1] * is0);
                *(float2*)&out[((size_t)r1 * SS + (t - 1)) * NN + ncg[j * 2]] =
                    make_float2(ek[4 + j * 2] * is1, ek[4 + j * 2 + 1] * is1);
            }
        }

        // ---- GEMM: 8 K-stages of 256; A via 3-stage TMA pipeline, W persistent ----
#pragma unroll 1
        for (int kb = 0; kb < NKB; kb++) {
            const int slot = cs;
            mbar_wait(mb[slot], (unsigned)cph);
            const unsigned aB = aRow + slot * A_STG;
            const unsigned bB = bRow + kb * W_STG;
#pragma unroll
            for (int kkIdx = 0; kkIdx < KBLK / 16; kkIdx++) {
                unsigned a0, a1, a2, a3, b0, b1, b2, b3;
                unsigned aA = aB + ((unsigned)((kkIdx * 2 + halfA) ^ mA) << 4);
                unsigned bA = bB + ((unsigned)((kkIdx * 2 + halfB) ^ mB) << 4);
                asm volatile("ldmatrix.sync.aligned.m8n8.x4.shared.b16 {%0,%1,%2,%3},[%4];"
                             : "=r"(a0), "=r"(a1), "=r"(a2), "=r"(a3) : "r"(aA));
                asm volatile("ldmatrix.sync.aligned.m8n8.x4.shared.b16 {%0,%1,%2,%3},[%4];"
                             : "=r"(b0), "=r"(b1), "=r"(b2), "=r"(b3) : "r"(bA));
                asm volatile("mma.sync.aligned.m16n8k16.row.col.f32.bf16.bf16.f32 "
                             "{%0,%1,%2,%3},{%4,%5,%6,%7},{%8,%9},{%0,%1,%2,%3};"
                             : "+f"(acc[0][0]), "+f"(acc[0][1]), "+f"(acc[0][2]), "+f"(acc[0][3])
                             : "r"(a0), "r"(a1), "r"(a2), "r"(a3), "r"(b0), "r"(b1));
                asm volatile("mma.sync.aligned.m16n8k16.row.col.f32.bf16.bf16.f32 "
                             "{%0,%1,%2,%3},{%4,%5,%6,%7},{%8,%9},{%0,%1,%2,%3};"
                             : "+f"(acc[1][0]), "+f"(acc[1][1]), "+f"(acc[1][2]), "+f"(acc[1][3])
                             : "r"(a0), "r"(a1), "r"(a2), "r"(a3), "r"(b2), "r"(b3));
            }
            __syncthreads();   // all warps done with this A slot
            if (kb + PIPE < NKB && tid == 0) {
                mbar_expect(mb[slot], A_STG);
                bulk_ld(smemA + slot * A_STG, eBuf + (size_t)(kb + PIPE) * A_STG, A_STG, mb[slot]);
            }
            ADV(cs, cph);
        }

        // ---- epilogue: z = lin + zrec/s_prev ; e = exp(z) ----
        float se0 = 0.f, se1 = 0.f;
#pragma unroll
        for (int j = 0; j < 2; j++)
#pragma unroll
            for (int q = 0; q < 2; q++) {
                int idx = j * 2 + q;
                float lin0 = fmaf(sV0[r0], wl0[idx], fmaf(sV1[r0], wl1[idx], bl4[idx]));
                float lin1 = fmaf(sV0[r1], wl0[idx], fmaf(sV1[r1], wl1[idx], bl4[idx]));
                float e0 = __expf(fmaf(acc[j][q],     is0, lin0));
                float e1 = __expf(fmaf(acc[j][2 + q], is1, lin1));
                ek[idx] = e0; ek[4 + idx] = e1;
                se0 += e0; se1 += e1;
                acc[j][q] = 0.f; acc[j][2 + q] = 0.f;
            }
        // store e into tiled+swizzled layout for next step's bulk loads
        unsigned char* ecur = g_e2[t & 1];
#pragma unroll
        for (int j = 0; j < 2; j++) {
            int n = ncg[j * 2];
            int kb2 = n >> 8, cb = (n & 255) * 2;
            unsigned sw0 = (unsigned)(((cb >> 4) ^ (r0 & 7)) << 4) | (cb & 15);
            unsigned sw1 = (unsigned)(((cb >> 4) ^ (r1 & 7)) << 4) | (cb & 15);
            *(__nv_bfloat162*)(ecur + (size_t)kb2 * A_STG + r0 * ROWB + sw0) =
                __floats2bfloat162_rn(ek[j * 2], ek[j * 2 + 1]);
            *(__nv_bfloat162*)(ecur + (size_t)kb2 * A_STG + r1 * ROWB + sw1) =
                __floats2bfloat162_rn(ek[4 + j * 2], ek[4 + j * 2 + 1]);
        }
        // deterministic per-CTA row partials
        se0 += __shfl_xor_sync(0xffffffffu, se0, 1); se0 += __shfl_xor_sync(0xffffffffu, se0, 2);
        se1 += __shfl_xor_sync(0xffffffffu, se1, 1); se1 += __shfl_xor_sync(0xffffffffu, se1, 2);
        if (tg == 0) { sWp[w >> 2][r0] = se0; sWp[w >> 2][r1] = se1; }
        __syncthreads();
        if (tid < BB) __stcg(&g_Sp[t & 1][blockIdx.x][tid], sWp[0][tid] + sWp[1][tid]);

        grid_bar(tid, (unsigned)(t + 1));
    }

    // ---- final step output (t = SS-1) ----
    if (tid < BB) {
        const float* pp = &g_Sp[(SS - 1) & 1][0][0] + tid;
        float s = 0.f;
#pragma unroll
        for (int c = 0; c < NCTA; c++) s += __ldcg(pp + c * BB);
        sInv[tid] = 1.f / s;
    }
    __syncthreads();
    {
        const float is0 = sInv[r0], is1 = sInv[r1];
#pragma unroll
        for (int j = 0; j < 2; j++) {
            *(float2*)&out[((size_t)r0 * SS + (SS - 1)) * NN + ncg[j * 2]] =
                make_float2(ek[j * 2] * is0, ek[j * 2 + 1] * is0);
            *(float2*)&out[((size_t)r1 * SS + (SS - 1)) * NN + ncg[j * 2]] =
                make_float2(ek[4 + j * 2] * is1, ek[4 + j * 2 + 1] * is1);
        }
    }
}

extern "C" void kernel_launch(void* const* d_in, const int* in_sizes, int n_in,
                              void* d_out, int out_size) {
    const float* vel  = (const float*)d_in[0];
    const float* h0   = (const float*)d_in[1];
    const float* Wlin = (const float*)d_in[2];
    const float* blin = (const float*)d_in[3];
    const float* Wrec = (const float*)d_in[4];
    float* out = (float*)d_out;
    static int configured = 0;
    if (!configured) {
        cudaFuncSetAttribute(k_step, cudaFuncAttributeMaxDynamicSharedMemorySize, DSM_BYTES);
        configured = 1;
    }
    k_setup<<<dim3(NCTA, NKB + 1), TPB>>>(Wrec, h0);
    k_step<<<NCTA, TPB, DSM_BYTES>>>(vel, Wlin, blin, out);
}